// round 12
// baseline (speedup 1.0000x reference)
#include <cuda_runtime.h>
#include <cuda_bf16.h>
#include <cuda_fp16.h>
#include <cstdint>

// Problem constants
#define NN 100000
#define FD 128
#define NEMAX 1600000
#define SCAN_BS 256
#define NB1 ((NN + SCAN_BS - 1) / SCAN_BS)   // 391

// ---------------- Scratch (static __device__, device-code access only) ------
__device__ __half g_hh[(size_t)NN * FD];    // GEMM output / messages (fp16)
__device__ __half g_aggh[(size_t)NN * FD];  // layer-1 activation * ns (fp16)
__device__ int   g_co[NN];                  // out-degree
__device__ int   g_ci[NN];                  // in-degree
__device__ int   g_rowptr[NN + 1];
__device__ int   g_cursor[NN];
__device__ int   g_esrc[NEMAX];
__device__ int   g_bsum[NB1];
// Transposed fp16 weights: [n][k]
__device__ __half g_w1h[FD * FD];
__device__ __half g_w2h[FD * FD];

// ---------------- Base-PTX MMA helpers ----------------
__device__ __forceinline__ uint32_t smem_u32(const void* p) {
    uint32_t a;
    asm("{ .reg .u64 t; cvta.to.shared.u64 t, %1; cvt.u32.u64 %0, t; }"
        : "=r"(a) : "l"(p));
    return a;
}
#define LDSM4(r0, r1, r2, r3, addr) \
    asm volatile("ldmatrix.sync.aligned.m8n8.x4.shared.b16 {%0,%1,%2,%3}, [%4];" \
                 : "=r"(r0), "=r"(r1), "=r"(r2), "=r"(r3) : "r"(addr))
#define LDSM2(r0, r1, addr) \
    asm volatile("ldmatrix.sync.aligned.m8n8.x2.shared.b16 {%0,%1}, [%2];" \
                 : "=r"(r0), "=r"(r1) : "r"(addr))
__device__ __forceinline__ void mma16816(float* c, const uint32_t* a, const uint32_t* b) {
    asm volatile("mma.sync.aligned.m16n8k16.row.col.f32.f16.f16.f32 "
                 "{%0,%1,%2,%3}, {%4,%5,%6,%7}, {%8,%9}, {%0,%1,%2,%3};"
                 : "+f"(c[0]), "+f"(c[1]), "+f"(c[2]), "+f"(c[3])
                 : "r"(a[0]), "r"(a[1]), "r"(a[2]), "r"(a[3]),
                   "r"(b[0]), "r"(b[1]));
}

// ---------------- Degree (scalar — R8-proven) ----------------
__global__ void degree_kernel(const int* __restrict__ src,
                              const int* __restrict__ dst, int E) {
    int i = blockIdx.x * blockDim.x + threadIdx.x;
    if (i < E) {
        atomicAdd(&g_co[__ldg(&src[i])], 1);
        atomicAdd(&g_ci[__ldg(&dst[i])], 1);
    }
}

// ---------------- Exclusive scan of g_ci -> g_rowptr (R8-proven) -------------
__global__ void scan1_kernel(int n) {
    __shared__ int s[SCAN_BS];
    int t = threadIdx.x, i = blockIdx.x * SCAN_BS + t;
    int v = (i < n) ? g_ci[i] : 0;
    s[t] = v; __syncthreads();
#pragma unroll
    for (int off = 1; off < SCAN_BS; off <<= 1) {
        int x = (t >= off) ? s[t - off] : 0; __syncthreads();
        s[t] += x; __syncthreads();
    }
    if (i < n) g_rowptr[i] = s[t] - v;
    if (t == SCAN_BS - 1) g_bsum[blockIdx.x] = s[t];
}
__global__ void scan2_kernel(int nb) {
    __shared__ int s[512];
    int t = threadIdx.x;
    int v = (t < nb) ? g_bsum[t] : 0;
    s[t] = v; __syncthreads();
#pragma unroll
    for (int off = 1; off < 512; off <<= 1) {
        int x = (t >= off) ? s[t - off] : 0; __syncthreads();
        s[t] += x; __syncthreads();
    }
    if (t < nb) g_bsum[t] = s[t] - v;
}
__global__ void scan3_kernel(int n, int E) {
    int i = blockIdx.x * blockDim.x + threadIdx.x;
    if (i < n) {
        int r = g_rowptr[i] + g_bsum[i >> 8];
        g_rowptr[i] = r; g_cursor[i] = r;
    }
    if (i == 0) g_rowptr[n] = E;
}

// ---------------- CSR fill (scalar — R8-proven) ----------------
__global__ void fill_kernel(const int* __restrict__ src,
                            const int* __restrict__ dst, int E) {
    int e = blockIdx.x * blockDim.x + threadIdx.x;
    if (e < E) {
        int pos = atomicAdd(&g_cursor[__ldg(&dst[e])], 1);
        g_esrc[pos] = __ldg(&src[e]);
    }
}

// ---------------- Weight prep: transpose to [n][k], fp16 ----------------
__global__ void prep_w_kernel(const float* __restrict__ W1,
                              const float* __restrict__ W2) {
    int i = blockIdx.x * blockDim.x + threadIdx.x;
    if (i < FD * FD) {
        int k = i >> 7, n = i & 127;
        g_w1h[n * FD + k] = __float2half(W1[i]);
        g_w2h[n * FD + k] = __float2half(W2[i]);
    }
}

// ---------------- fp16 mma.sync GEMM, 128x64 block tile ----------------------
// g_hh = A16 @ W16 (fp32 acc). Layer 1: A = fp16(features * ns) on the fly.
// Layer 2: A = g_aggh (fp16, *ns folded) — straight copy.
// Grid: 2 CTAs per 128-row band; bx>>1 = row band, bx&1 = 64-col half.
// 8 warps as 4(m) x 2(n); warp tile 32x32; 3 CTAs/SM.
#define ASTRIDE 136
#define TILE_A (128 * ASTRIDE * 2)   // 34816 bytes
#define TILE_BB (64 * ASTRIDE * 2)   // 17408 bytes
#define OFF_A 0
#define OFF_B TILE_A
#define GEMM_SMEM (TILE_A + TILE_BB) // 52224 bytes

__global__ __launch_bounds__(256, 3) void gemm_mma_kernel(
    const float* __restrict__ Aext, int layer, int M) {
    extern __shared__ char sm[];
    const uint32_t sb = smem_u32(sm);
    const int tid = threadIdx.x;
    const int lane = tid & 31;
    const int wid = tid >> 5;
    const int row0 = (blockIdx.x >> 1) * 128;
    const int ncol0 = (blockIdx.x & 1) * 64;

    // ---- Fill A tile (128 x 128): thread handles row tid/2, 64-col half ----
    {
        int r = tid >> 1;
        int cs = (tid & 1) * 64;
        int grow = row0 + r;
        uint32_t base = (uint32_t)(r * ASTRIDE + cs) * 2;
        if (layer == 1) {
            if (grow < M) {
                float nm = rsqrtf(fmaxf((float)__ldg(&g_co[grow]), 1.f));
                const float4* ap = reinterpret_cast<const float4*>(Aext + (size_t)grow * FD + cs);
#pragma unroll
                for (int j = 0; j < 16; j++) {
                    float4 v = __ldg(&ap[j]);
                    __half2 p0 = __floats2half2_rn(v.x * nm, v.y * nm);
                    __half2 p1 = __floats2half2_rn(v.z * nm, v.w * nm);
                    uint32_t o = base + j * 8;
                    *reinterpret_cast<uint32_t*>(sm + OFF_A + o)     = *reinterpret_cast<uint32_t*>(&p0);
                    *reinterpret_cast<uint32_t*>(sm + OFF_A + o + 4) = *reinterpret_cast<uint32_t*>(&p1);
                }
            } else {
#pragma unroll
                for (int j = 0; j < 16; j++) {
                    uint32_t o = base + j * 8;
                    *reinterpret_cast<uint32_t*>(sm + OFF_A + o)     = 0u;
                    *reinterpret_cast<uint32_t*>(sm + OFF_A + o + 4) = 0u;
                }
            }
        } else {
            if (grow < M) {
                const uint4* ap = reinterpret_cast<const uint4*>(g_aggh + (size_t)grow * FD + cs);
#pragma unroll
                for (int j = 0; j < 8; j++)
                    *reinterpret_cast<uint4*>(sm + OFF_A + base + j * 16) = __ldg(&ap[j]);
            } else {
#pragma unroll
                for (int j = 0; j < 8; j++)
                    *reinterpret_cast<uint4*>(sm + OFF_A + base + j * 16) =
                        make_uint4(0u, 0u, 0u, 0u);
            }
        }
    }
    // ---- Fill B tile (64 rows x 128 k): thread handles row tid/4, 32-half seg
    {
        const __half* wh = (layer == 1) ? g_w1h : g_w2h;
        int n = tid >> 2;                 // 0..63
        int seg = (tid & 3) * 32;         // halves
        uint32_t base = (uint32_t)(n * ASTRIDE + seg) * 2;
        const uint4* ph = reinterpret_cast<const uint4*>(wh + (size_t)(ncol0 + n) * FD + seg);
#pragma unroll
        for (int j = 0; j < 4; j++)       // 4 x 8 halves = 32
            *reinterpret_cast<uint4*>(sm + OFF_B + base + j * 16) = __ldg(&ph[j]);
    }
    __syncthreads();

    // ---- Mainloop: warp tile 32x32; warps 4(m) x 2(n) ----
    const int m0 = (wid >> 1) * 32;
    const int n0 = (wid & 1) * 32;

    float acc[2][4][4];
#pragma unroll
    for (int mi = 0; mi < 2; mi++)
#pragma unroll
        for (int ni = 0; ni < 4; ni++)
#pragma unroll
            for (int q = 0; q < 4; q++) acc[mi][ni][q] = 0.f;

    const uint32_t aOff = (uint32_t)((m0 + (lane & 15)) * ASTRIDE + ((lane >> 4) << 3)) * 2;
    const uint32_t bOff = (uint32_t)((n0 + (lane & 7)) * ASTRIDE + (((lane >> 3) & 1) << 3)) * 2;
    const uint32_t aBase = sb + OFF_A + aOff;
    const uint32_t bBase = sb + OFF_B + bOff;

#pragma unroll
    for (int ks = 0; ks < 8; ks++) {
        const uint32_t ka = ks * 32;
        uint32_t a[2][4], b[4][2];
#pragma unroll
        for (int mi = 0; mi < 2; mi++)
            LDSM4(a[mi][0], a[mi][1], a[mi][2], a[mi][3], aBase + mi * (16 * ASTRIDE * 2) + ka);
#pragma unroll
        for (int ni = 0; ni < 4; ni++)
            LDSM2(b[ni][0], b[ni][1], bBase + ni * (8 * ASTRIDE * 2) + ka);
#pragma unroll
        for (int mi = 0; mi < 2; mi++)
#pragma unroll
            for (int ni = 0; ni < 4; ni++)
                mma16816(acc[mi][ni], a[mi], b[ni]);
    }

    // ---- Epilogue: fragment -> g_hh (fp16) ----
    const int rb = m0 + (lane >> 2);
    const int cb = ncol0 + n0 + (lane & 3) * 2;
#pragma unroll
    for (int mi = 0; mi < 2; mi++) {
        int r0g = row0 + rb + mi * 16;
#pragma unroll
        for (int ni = 0; ni < 4; ni++) {
            int col = cb + ni * 8;
            if (r0g < M)
                *reinterpret_cast<__half2*>(g_hh + (size_t)r0g * FD + col) =
                    __floats2half2_rn(acc[mi][ni][0], acc[mi][ni][1]);
            if (r0g + 8 < M)
                *reinterpret_cast<__half2*>(g_hh + (size_t)(r0g + 8) * FD + col) =
                    __floats2half2_rn(acc[mi][ni][2], acc[mi][ni][3]);
        }
    }
}

// ---------------- CSR aggregate (fp16 messages) + fused epilogue -------------
// norms inline: nd = rsqrt(max(deg_in,1)); ns = rsqrt(max(deg_out,1)).
// Layer 1 (out==nullptr): g_aggh = fp16(relu(acc*nd + b) * ns)
// Layer 2: out = acc*nd + b  (fp32)
__global__ __launch_bounds__(256) void agg_kernel(
    const float* __restrict__ bvec, float* __restrict__ out, int M) {
    const int warp = (blockIdx.x * blockDim.x + threadIdx.x) >> 5;
    const int lane = threadIdx.x & 31;
    if (warp >= M) return;

    const int beg = __ldg(&g_rowptr[warp]);
    const int end = __ldg(&g_rowptr[warp + 1]);

    float4 acc = make_float4(0.f, 0.f, 0.f, 0.f);
    int j = beg;
    for (; j + 3 < end; j += 4) {
        int s0 = __ldg(&g_esrc[j]);
        int s1 = __ldg(&g_esrc[j + 1]);
        int s2 = __ldg(&g_esrc[j + 2]);
        int s3 = __ldg(&g_esrc[j + 3]);
        uint2 u0 = __ldg(reinterpret_cast<const uint2*>(g_hh + (size_t)s0 * FD) + lane);
        uint2 u1 = __ldg(reinterpret_cast<const uint2*>(g_hh + (size_t)s1 * FD) + lane);
        uint2 u2 = __ldg(reinterpret_cast<const uint2*>(g_hh + (size_t)s2 * FD) + lane);
        uint2 u3 = __ldg(reinterpret_cast<const uint2*>(g_hh + (size_t)s3 * FD) + lane);
#pragma unroll
        for (int q = 0; q < 4; q++) {
            uint2 u = (q == 0) ? u0 : (q == 1) ? u1 : (q == 2) ? u2 : u3;
            float2 fa = __half22float2(*reinterpret_cast<__half2*>(&u.x));
            float2 fb = __half22float2(*reinterpret_cast<__half2*>(&u.y));
            acc.x += fa.x; acc.y += fa.y; acc.z += fb.x; acc.w += fb.y;
        }
    }
    for (; j < end; j++) {
        int s0 = __ldg(&g_esrc[j]);
        uint2 u = __ldg(reinterpret_cast<const uint2*>(g_hh + (size_t)s0 * FD) + lane);
        float2 fa = __half22float2(*reinterpret_cast<__half2*>(&u.x));
        float2 fb = __half22float2(*reinterpret_cast<__half2*>(&u.y));
        acc.x += fa.x; acc.y += fa.y; acc.z += fb.x; acc.w += fb.y;
    }

    const float nd = rsqrtf(fmaxf((float)__ldg(&g_ci[warp]), 1.f));
    const float4 bb = __ldg(reinterpret_cast<const float4*>(bvec) + lane);
    acc.x = acc.x * nd + bb.x; acc.y = acc.y * nd + bb.y;
    acc.z = acc.z * nd + bb.z; acc.w = acc.w * nd + bb.w;

    if (out) {
        reinterpret_cast<float4*>(out + (size_t)warp * FD)[lane] = acc;
    } else {
        const float ns = rsqrtf(fmaxf((float)__ldg(&g_co[warp]), 1.f));
        acc.x = fmaxf(acc.x, 0.f) * ns; acc.y = fmaxf(acc.y, 0.f) * ns;
        acc.z = fmaxf(acc.z, 0.f) * ns; acc.w = fmaxf(acc.w, 0.f) * ns;
        __half2 p0 = __floats2half2_rn(acc.x, acc.y);
        __half2 p1 = __floats2half2_rn(acc.z, acc.w);
        uint2 u;
        u.x = *reinterpret_cast<uint32_t*>(&p0);
        u.y = *reinterpret_cast<uint32_t*>(&p1);
        reinterpret_cast<uint2*>(g_aggh + (size_t)warp * FD)[lane] = u;
    }
}

// ---------------- Launch (R8-proven ordering) ----------------
extern "C" void kernel_launch(void* const* d_in, const int* in_sizes, int n_in,
                              void* d_out, int out_size) {
    const float* features = (const float*)d_in[0];
    const int* src = (const int*)d_in[1];
    const int* dst = (const int*)d_in[2];
    const float* W1 = (const float*)d_in[3];
    const float* b1 = (const float*)d_in[4];
    const float* W2 = (const float*)d_in[5];
    const float* b2 = (const float*)d_in[6];
    float* out = (float*)d_out;

    const int M = in_sizes[0] / FD;   // 100000
    const int E = in_sizes[1];        // 1600000

    // One-time resource setup (host objects + symbol addresses; no allocation)
    static cudaStream_t s2 = nullptr;
    static cudaEvent_t evA = nullptr, evB = nullptr;
    static void* p_co = nullptr;
    static void* p_ci = nullptr;
    if (!s2) {
        cudaStreamCreateWithFlags(&s2, cudaStreamNonBlocking);
        cudaEventCreateWithFlags(&evA, cudaEventDisableTiming);
        cudaEventCreateWithFlags(&evB, cudaEventDisableTiming);
        cudaGetSymbolAddress(&p_co, g_co);
        cudaGetSymbolAddress(&p_ci, g_ci);
        cudaFuncSetAttribute(gemm_mma_kernel,
                             cudaFuncAttributeMaxDynamicSharedMemorySize, GEMM_SMEM);
    }

    const int T = 256;
    const int mb = (M + T - 1) / T;
    const int eb = (E + T - 1) / T;

    // Legacy stream: zero counters (memset nodes), degree
    cudaMemsetAsync(p_co, 0, (size_t)M * sizeof(int), (cudaStream_t)0);
    cudaMemsetAsync(p_ci, 0, (size_t)M * sizeof(int), (cudaStream_t)0);
    degree_kernel<<<eb, T>>>(src, dst, E);
    cudaEventRecord(evA, (cudaStream_t)0);

    // Fork: CSR build on s2, concurrent with prep+gemm1
    cudaStreamWaitEvent(s2, evA, 0);
    scan1_kernel<<<NB1, SCAN_BS, 0, s2>>>(M);
    scan2_kernel<<<1, 512, 0, s2>>>(NB1);
    scan3_kernel<<<mb, T, 0, s2>>>(M, E);
    fill_kernel<<<eb, T, 0, s2>>>(src, dst, E);
    cudaEventRecord(evB, s2);

    // Legacy stream: weight prep, layer-1 GEMM (ns inline from g_co)
    prep_w_kernel<<<(FD * FD + T - 1) / T, T>>>(W1, W2);

    const int gemm_blocks = ((M + 127) / 128) * 2;  // 1564 (2 per row band)
    const int agg_blocks = (M * 32 + T - 1) / T;    // one warp per node

    gemm_mma_kernel<<<gemm_blocks, 256, GEMM_SMEM>>>(features, 1, M);

    // Join: agg1 needs the CSR
    cudaStreamWaitEvent((cudaStream_t)0, evB, 0);
    agg_kernel<<<agg_blocks, T>>>(b1, nullptr, M);

    // Layer 2
    gemm_mma_kernel<<<gemm_blocks, 256, GEMM_SMEM>>>(nullptr, 2, M);
    agg_kernel<<<agg_blocks, T>>>(b2, out, M);
}

// round 14
// speedup vs baseline: 1.0424x; 1.0424x over previous
#include <cuda_runtime.h>
#include <cuda_bf16.h>
#include <cuda_fp16.h>
#include <cstdint>

// Problem constants
#define NN 100000
#define FD 128
#define NEMAX 1600000
#define SCAN_BS 256
#define NB1 ((NN + SCAN_BS - 1) / SCAN_BS)   // 391
#define HALF_ROWS 50048                       // 391 * 128, row-band aligned

// ---------------- Scratch (static __device__, device-code access only) ------
__device__ __half g_hh[(size_t)NN * FD];    // layer-1 messages (fp16)
__device__ __half g_hh2[(size_t)NN * FD];   // layer-2 messages (fp16) — NO aliasing
__device__ __half g_aggh[(size_t)NN * FD];  // layer-1 activation * ns (fp16)
__device__ float g_ns[NN];                  // norm_src
__device__ float g_nd[NN];                  // norm_dst
__device__ int   g_co[NN];
__device__ int   g_ci[NN];
__device__ int   g_rowptr[NN + 1];
__device__ int   g_cursor[NN];
__device__ int   g_esrc[NEMAX];
__device__ int   g_bsum[NB1];
// Transposed fp16 weights: [n][k]
__device__ __half g_w1h[FD * FD];
__device__ __half g_w2h[FD * FD];

// ---------------- Base-PTX MMA helpers ----------------
__device__ __forceinline__ uint32_t smem_u32(const void* p) {
    uint32_t a;
    asm("{ .reg .u64 t; cvta.to.shared.u64 t, %1; cvt.u32.u64 %0, t; }"
        : "=r"(a) : "l"(p));
    return a;
}
#define LDSM4(r0, r1, r2, r3, addr) \
    asm volatile("ldmatrix.sync.aligned.m8n8.x4.shared.b16 {%0,%1,%2,%3}, [%4];" \
                 : "=r"(r0), "=r"(r1), "=r"(r2), "=r"(r3) : "r"(addr))
#define LDSM2(r0, r1, addr) \
    asm volatile("ldmatrix.sync.aligned.m8n8.x2.shared.b16 {%0,%1}, [%2];" \
                 : "=r"(r0), "=r"(r1) : "r"(addr))
__device__ __forceinline__ void mma16816(float* c, const uint32_t* a, const uint32_t* b) {
    asm volatile("mma.sync.aligned.m16n8k16.row.col.f32.f16.f16.f32 "
                 "{%0,%1,%2,%3}, {%4,%5,%6,%7}, {%8,%9}, {%0,%1,%2,%3};"
                 : "+f"(c[0]), "+f"(c[1]), "+f"(c[2]), "+f"(c[3])
                 : "r"(a[0]), "r"(a[1]), "r"(a[2]), "r"(a[3]),
                   "r"(b[0]), "r"(b[1]));
}

// ---------------- Counters / norms / CSR (R8-proven) ----------------
__global__ void zero_cnt_kernel(int n) {
    int i = blockIdx.x * blockDim.x + threadIdx.x;
    if (i < n) { g_co[i] = 0; g_ci[i] = 0; }
}
__global__ void degree_kernel(const int* __restrict__ src,
                              const int* __restrict__ dst, int E) {
    int i = blockIdx.x * blockDim.x + threadIdx.x;
    if (i < E) { atomicAdd(&g_co[src[i]], 1); atomicAdd(&g_ci[dst[i]], 1); }
}
__global__ void norm_kernel(int n) {
    int i = blockIdx.x * blockDim.x + threadIdx.x;
    if (i < n) {
        g_ns[i] = rsqrtf(fmaxf((float)g_co[i], 1.f));
        g_nd[i] = rsqrtf(fmaxf((float)g_ci[i], 1.f));
    }
}
__global__ void scan1_kernel(int n) {
    __shared__ int s[SCAN_BS];
    int t = threadIdx.x, i = blockIdx.x * SCAN_BS + t;
    int v = (i < n) ? g_ci[i] : 0;
    s[t] = v; __syncthreads();
#pragma unroll
    for (int off = 1; off < SCAN_BS; off <<= 1) {
        int x = (t >= off) ? s[t - off] : 0; __syncthreads();
        s[t] += x; __syncthreads();
    }
    if (i < n) g_rowptr[i] = s[t] - v;
    if (t == SCAN_BS - 1) g_bsum[blockIdx.x] = s[t];
}
__global__ void scan2_kernel(int nb) {
    __shared__ int s[512];
    int t = threadIdx.x;
    int v = (t < nb) ? g_bsum[t] : 0;
    s[t] = v; __syncthreads();
#pragma unroll
    for (int off = 1; off < 512; off <<= 1) {
        int x = (t >= off) ? s[t - off] : 0; __syncthreads();
        s[t] += x; __syncthreads();
    }
    if (t < nb) g_bsum[t] = s[t] - v;
}
__global__ void scan3_kernel(int n, int E) {
    int i = blockIdx.x * blockDim.x + threadIdx.x;
    if (i < n) {
        int r = g_rowptr[i] + g_bsum[i >> 8];
        g_rowptr[i] = r; g_cursor[i] = r;
    }
    if (i == 0) g_rowptr[n] = E;
}
__global__ void fill_kernel(const int* __restrict__ src,
                            const int* __restrict__ dst, int E) {
    int e = blockIdx.x * blockDim.x + threadIdx.x;
    if (e < E) {
        int pos = atomicAdd(&g_cursor[dst[e]], 1);
        g_esrc[pos] = src[e];
    }
}
__global__ void prep_w_kernel(const float* __restrict__ W1,
                              const float* __restrict__ W2) {
    int i = blockIdx.x * blockDim.x + threadIdx.x;
    if (i < FD * FD) {
        int k = i >> 7, n = i & 127;
        g_w1h[n * FD + k] = __float2half(W1[i]);
        g_w2h[n * FD + k] = __float2half(W2[i]);
    }
}

// ---------------- fp16 mma.sync GEMM (R8-proven 128x128 tile) ----------------
// Row-range variant: rows [rowbase, Mlim).
// Layer 1: A = fp16(features * ns), writes g_hh.
// Layer 2: A = g_aggh (fp16, *ns folded), writes g_hh2.
#define ASTRIDE 136
#define TILE_B (128 * ASTRIDE * 2)   // 34816 bytes
#define OFF_A 0
#define OFF_B TILE_B
#define GEMM_SMEM (2 * TILE_B)       // 69632 bytes

__global__ __launch_bounds__(256) void gemm_mma_kernel(
    const float* __restrict__ Aext, int layer, int rowbase, int Mlim) {
    extern __shared__ char sm[];
    const uint32_t sb = smem_u32(sm);
    const int tid = threadIdx.x;
    const int lane = tid & 31;
    const int wid = tid >> 5;
    const int row0 = rowbase + blockIdx.x * 128;

    // ---- Fill A tile: thread handles row tid/2, 64-col half ----
    {
        int r = tid >> 1;
        int cs = (tid & 1) * 64;
        int grow = row0 + r;
        uint32_t base = (uint32_t)(r * ASTRIDE + cs) * 2;
        if (layer == 1) {
            if (grow < Mlim) {
                float nm = g_ns[grow];
                const float4* ap = reinterpret_cast<const float4*>(Aext + (size_t)grow * FD + cs);
#pragma unroll
                for (int j = 0; j < 16; j++) {
                    float4 v = __ldg(&ap[j]);
                    __half2 p0 = __floats2half2_rn(v.x * nm, v.y * nm);
                    __half2 p1 = __floats2half2_rn(v.z * nm, v.w * nm);
                    uint32_t o = base + j * 8;
                    *reinterpret_cast<uint32_t*>(sm + OFF_A + o)     = *reinterpret_cast<uint32_t*>(&p0);
                    *reinterpret_cast<uint32_t*>(sm + OFF_A + o + 4) = *reinterpret_cast<uint32_t*>(&p1);
                }
            } else {
#pragma unroll
                for (int j = 0; j < 16; j++) {
                    uint32_t o = base + j * 8;
                    *reinterpret_cast<uint32_t*>(sm + OFF_A + o)     = 0u;
                    *reinterpret_cast<uint32_t*>(sm + OFF_A + o + 4) = 0u;
                }
            }
        } else {
            if (grow < Mlim) {
                const uint4* ap = reinterpret_cast<const uint4*>(g_aggh + (size_t)grow * FD + cs);
#pragma unroll
                for (int j = 0; j < 8; j++)
                    *reinterpret_cast<uint4*>(sm + OFF_A + base + j * 16) = __ldg(&ap[j]);
            } else {
#pragma unroll
                for (int j = 0; j < 8; j++)
                    *reinterpret_cast<uint4*>(sm + OFF_A + base + j * 16) =
                        make_uint4(0u, 0u, 0u, 0u);
            }
        }
    }
    // ---- Fill B tile from pre-transposed fp16 weights [n][k] ----
    {
        const __half* wh = (layer == 1) ? g_w1h : g_w2h;
        int n = tid >> 1;
        int cs = (tid & 1) * 64;
        uint32_t base = (uint32_t)(n * ASTRIDE + cs) * 2;
        const uint4* ph = reinterpret_cast<const uint4*>(wh + (size_t)n * FD + cs);
#pragma unroll
        for (int j = 0; j < 8; j++)
            *reinterpret_cast<uint4*>(sm + OFF_B + base + j * 16) = __ldg(&ph[j]);
    }
    __syncthreads();

    // ---- Mainloop: warp tile 64x32, 8 warps (2x4) ----
    const int m0 = (wid >> 2) * 64;
    const int n0 = (wid & 3) * 32;

    float acc[4][4][4];
#pragma unroll
    for (int mi = 0; mi < 4; mi++)
#pragma unroll
        for (int ni = 0; ni < 4; ni++)
#pragma unroll
            for (int q = 0; q < 4; q++) acc[mi][ni][q] = 0.f;

    const uint32_t aOff = (uint32_t)((m0 + (lane & 15)) * ASTRIDE + ((lane >> 4) << 3)) * 2;
    const uint32_t bOff = (uint32_t)((n0 + (lane & 7)) * ASTRIDE + (((lane >> 3) & 1) << 3)) * 2;
    const uint32_t aBase = sb + OFF_A + aOff;
    const uint32_t bBase = sb + OFF_B + bOff;

#pragma unroll
    for (int ks = 0; ks < 8; ks++) {
        const uint32_t ka = ks * 32;
        uint32_t a[4][4], b[4][2];
#pragma unroll
        for (int mi = 0; mi < 4; mi++)
            LDSM4(a[mi][0], a[mi][1], a[mi][2], a[mi][3], aBase + mi * (16 * ASTRIDE * 2) + ka);
#pragma unroll
        for (int ni = 0; ni < 4; ni++)
            LDSM2(b[ni][0], b[ni][1], bBase + ni * (8 * ASTRIDE * 2) + ka);
#pragma unroll
        for (int mi = 0; mi < 4; mi++)
#pragma unroll
            for (int ni = 0; ni < 4; ni++)
                mma16816(acc[mi][ni], a[mi], b[ni]);
    }

    // ---- Epilogue: fragment -> message buffer (fp16) ----
    __half* hout = (layer == 1) ? g_hh : g_hh2;
    const int rb = m0 + (lane >> 2);
    const int cb = n0 + (lane & 3) * 2;
#pragma unroll
    for (int mi = 0; mi < 4; mi++) {
        int r0g = row0 + rb + mi * 16;
#pragma unroll
        for (int ni = 0; ni < 4; ni++) {
            int col = cb + ni * 8;
            if (r0g < Mlim)
                *reinterpret_cast<__half2*>(hout + (size_t)r0g * FD + col) =
                    __floats2half2_rn(acc[mi][ni][0], acc[mi][ni][1]);
            if (r0g + 8 < Mlim)
                *reinterpret_cast<__half2*>(hout + (size_t)(r0g + 8) * FD + col) =
                    __floats2half2_rn(acc[mi][ni][2], acc[mi][ni][3]);
        }
    }
}

// ---------------- CSR aggregate (R8-proven) + row-range + buffer select ------
// Layer 1 (out==nullptr): reads g_hh,  writes g_aggh = fp16(relu(acc*nd+b)*ns)
// Layer 2 (out!=nullptr): reads g_hh2, writes out = acc*nd + b (fp32)
__global__ __launch_bounds__(256) void agg_kernel(
    const float* __restrict__ bvec, float* __restrict__ out,
    int rowbase, int Mlim) {
    const int warp = rowbase + ((blockIdx.x * blockDim.x + threadIdx.x) >> 5);
    const int lane = threadIdx.x & 31;
    if (warp >= Mlim) return;

    const __half* hbuf = out ? g_hh2 : g_hh;
    const int beg = __ldg(&g_rowptr[warp]);
    const int end = __ldg(&g_rowptr[warp + 1]);

    float4 acc = make_float4(0.f, 0.f, 0.f, 0.f);
    int j = beg;
    for (; j + 3 < end; j += 4) {
        int s0 = __ldg(&g_esrc[j]);
        int s1 = __ldg(&g_esrc[j + 1]);
        int s2 = __ldg(&g_esrc[j + 2]);
        int s3 = __ldg(&g_esrc[j + 3]);
        uint2 u0 = __ldg(reinterpret_cast<const uint2*>(hbuf + (size_t)s0 * FD) + lane);
        uint2 u1 = __ldg(reinterpret_cast<const uint2*>(hbuf + (size_t)s1 * FD) + lane);
        uint2 u2 = __ldg(reinterpret_cast<const uint2*>(hbuf + (size_t)s2 * FD) + lane);
        uint2 u3 = __ldg(reinterpret_cast<const uint2*>(hbuf + (size_t)s3 * FD) + lane);
#pragma unroll
        for (int q = 0; q < 4; q++) {
            uint2 u = (q == 0) ? u0 : (q == 1) ? u1 : (q == 2) ? u2 : u3;
            float2 fa = __half22float2(*reinterpret_cast<__half2*>(&u.x));
            float2 fb = __half22float2(*reinterpret_cast<__half2*>(&u.y));
            acc.x += fa.x; acc.y += fa.y; acc.z += fb.x; acc.w += fb.y;
        }
    }
    for (; j < end; j++) {
        int s0 = __ldg(&g_esrc[j]);
        uint2 u = __ldg(reinterpret_cast<const uint2*>(hbuf + (size_t)s0 * FD) + lane);
        float2 fa = __half22float2(*reinterpret_cast<__half2*>(&u.x));
        float2 fb = __half22float2(*reinterpret_cast<__half2*>(&u.y));
        acc.x += fa.x; acc.y += fa.y; acc.z += fb.x; acc.w += fb.y;
    }

    const float nd = g_nd[warp];
    const float4 bb = __ldg(reinterpret_cast<const float4*>(bvec) + lane);
    acc.x = acc.x * nd + bb.x; acc.y = acc.y * nd + bb.y;
    acc.z = acc.z * nd + bb.z; acc.w = acc.w * nd + bb.w;

    if (out) {
        reinterpret_cast<float4*>(out + (size_t)warp * FD)[lane] = acc;
    } else {
        const float ns = g_ns[warp];
        acc.x = fmaxf(acc.x, 0.f) * ns; acc.y = fmaxf(acc.y, 0.f) * ns;
        acc.z = fmaxf(acc.z, 0.f) * ns; acc.w = fmaxf(acc.w, 0.f) * ns;
        __half2 p0 = __floats2half2_rn(acc.x, acc.y);
        __half2 p1 = __floats2half2_rn(acc.z, acc.w);
        uint2 u;
        u.x = *reinterpret_cast<uint32_t*>(&p0);
        u.y = *reinterpret_cast<uint32_t*>(&p1);
        reinterpret_cast<uint2*>(g_aggh + (size_t)warp * FD)[lane] = u;
    }
}

// ---------------- Launch ----------------
extern "C" void kernel_launch(void* const* d_in, const int* in_sizes, int n_in,
                              void* d_out, int out_size) {
    const float* features = (const float*)d_in[0];
    const int* src = (const int*)d_in[1];
    const int* dst = (const int*)d_in[2];
    const float* W1 = (const float*)d_in[3];
    const float* b1 = (const float*)d_in[4];
    const float* W2 = (const float*)d_in[5];
    const float* b2 = (const float*)d_in[6];
    float* out = (float*)d_out;

    const int M = in_sizes[0] / FD;   // 100000
    const int E = in_sizes[1];        // 1600000

    static cudaStream_t s2 = nullptr;
    static cudaEvent_t evA = nullptr, evB = nullptr, evH0 = nullptr, evG0 = nullptr;
    if (!s2) {
        cudaStreamCreateWithFlags(&s2, cudaStreamNonBlocking);
        cudaEventCreateWithFlags(&evA, cudaEventDisableTiming);
        cudaEventCreateWithFlags(&evB, cudaEventDisableTiming);
        cudaEventCreateWithFlags(&evH0, cudaEventDisableTiming);
        cudaEventCreateWithFlags(&evG0, cudaEventDisableTiming);
        cudaFuncSetAttribute(gemm_mma_kernel,
                             cudaFuncAttributeMaxDynamicSharedMemorySize, GEMM_SMEM);
    }

    const int T = 256;
    const int mb = (M + T - 1) / T;
    const int eb = (E + T - 1) / T;

    const int h0 = (M < HALF_ROWS) ? M : HALF_ROWS;      // rows [0, h0)
    const int h1n = M - h0;                               // rows [h0, M)
    const int gemm_b_full = (M + 127) / 128;
    const int gemm_b_h0 = (h0 + 127) / 128;
    const int gemm_b_h1 = (h1n + 127) / 128;
    const int agg_b_h0 = (h0 * 32 + T - 1) / T;
    const int agg_b_h1 = (h1n * 32 + T - 1) / T;
    const int agg_b_full = (M * 32 + T - 1) / T;

    // Legacy stream: counters, degree, norms
    zero_cnt_kernel<<<mb, T>>>(M);
    degree_kernel<<<eb, T>>>(src, dst, E);
    norm_kernel<<<mb, T>>>(M);
    cudaEventRecord(evA, (cudaStream_t)0);

    // Fork: CSR build on s2, concurrent with prep+gemm1
    cudaStreamWaitEvent(s2, evA, 0);
    scan1_kernel<<<NB1, SCAN_BS, 0, s2>>>(M);
    scan2_kernel<<<1, 512, 0, s2>>>(NB1);
    scan3_kernel<<<mb, T, 0, s2>>>(M, E);
    fill_kernel<<<eb, T, 0, s2>>>(src, dst, E);
    cudaEventRecord(evB, s2);

    // Legacy stream: weight prep, layer-1 GEMM (full range) -> g_hh
    prep_w_kernel<<<(FD * FD + T - 1) / T, T>>>(W1, W2);
    gemm_mma_kernel<<<gemm_b_full, 256, GEMM_SMEM>>>(features, 1, 0, M);

    // Join with CSR, then pipelined agg1 / gemm2 by row halves.
    // Race-free: gemm2 writes g_hh2, agg1 reads g_hh (disjoint buffers);
    // gemm2 h0 reads only g_aggh[0,h0) which agg1 h0 completed (evH0).
    cudaStreamWaitEvent((cudaStream_t)0, evB, 0);
    agg_kernel<<<agg_b_h0, T>>>(b1, nullptr, 0, h0);      // agg1 rows [0,h0)
    cudaEventRecord(evH0, (cudaStream_t)0);

    // s2: gemm2 rows [0,h0) -> g_hh2, concurrent with agg1 rows [h0,M)
    cudaStreamWaitEvent(s2, evH0, 0);
    gemm_mma_kernel<<<gemm_b_h0, 256, GEMM_SMEM, s2>>>(nullptr, 2, 0, h0);
    cudaEventRecord(evG0, s2);

    // Legacy: agg1 rows [h0,M), then gemm2 rows [h0,M) -> g_hh2
    agg_kernel<<<agg_b_h1, T>>>(b1, nullptr, h0, M);
    gemm_mma_kernel<<<gemm_b_h1, 256, GEMM_SMEM>>>(nullptr, 2, h0, M);

    // agg2 needs both gemm2 halves (evG0 for the s2 half)
    cudaStreamWaitEvent((cudaStream_t)0, evG0, 0);
    agg_kernel<<<agg_b_full, T>>>(b2, out, 0, M);
}

// round 16
// speedup vs baseline: 1.0737x; 1.0300x over previous
#include <cuda_runtime.h>
#include <cuda_bf16.h>
#include <cuda_fp16.h>
#include <cstdint>

// Problem constants
#define NN 100000
#define FD 128
#define NEMAX 1600000
#define SCAN_BS 256
#define NB1 ((NN + SCAN_BS - 1) / SCAN_BS)   // 391

// ---------------- Scratch (static __device__, device-code access only) ------
__device__ __half g_hh[(size_t)NN * FD];    // GEMM output / messages (fp16)
__device__ __half g_aggh[(size_t)NN * FD];  // layer-1 activation * ns (fp16)
__device__ int   g_co[NN];                  // out-degree
__device__ int   g_ci[NN];                  // in-degree
__device__ int   g_rowptr[NN + 1];
__device__ int   g_cursor[NN];
__device__ int   g_esrc[NEMAX];
__device__ int   g_bsum[NB1];
// Transposed fp16 weights: [n][k]
__device__ __half g_w1h[FD * FD];
__device__ __half g_w2h[FD * FD];

// ---------------- Base-PTX MMA helpers ----------------
__device__ __forceinline__ uint32_t smem_u32(const void* p) {
    uint32_t a;
    asm("{ .reg .u64 t; cvta.to.shared.u64 t, %1; cvt.u32.u64 %0, t; }"
        : "=r"(a) : "l"(p));
    return a;
}
#define LDSM4(r0, r1, r2, r3, addr) \
    asm volatile("ldmatrix.sync.aligned.m8n8.x4.shared.b16 {%0,%1,%2,%3}, [%4];" \
                 : "=r"(r0), "=r"(r1), "=r"(r2), "=r"(r3) : "r"(addr))
#define LDSM2(r0, r1, addr) \
    asm volatile("ldmatrix.sync.aligned.m8n8.x2.shared.b16 {%0,%1}, [%2];" \
                 : "=r"(r0), "=r"(r1) : "r"(addr))
__device__ __forceinline__ void mma16816(float* c, const uint32_t* a, const uint32_t* b) {
    asm volatile("mma.sync.aligned.m16n8k16.row.col.f32.f16.f16.f32 "
                 "{%0,%1,%2,%3}, {%4,%5,%6,%7}, {%8,%9}, {%0,%1,%2,%3};"
                 : "+f"(c[0]), "+f"(c[1]), "+f"(c[2]), "+f"(c[3])
                 : "r"(a[0]), "r"(a[1]), "r"(a[2]), "r"(a[3]),
                   "r"(b[0]), "r"(b[1]));
}

// ---------------- Counters (memset replaced by kernel to keep capture simple)
__global__ void zero_cnt_kernel(int n) {
    int i = blockIdx.x * blockDim.x + threadIdx.x;
    if (i < n) { g_co[i] = 0; g_ci[i] = 0; }
}

// ---------------- Degree / CSR (R8-proven, scalar atomics) ----------------
__global__ void degree_kernel(const int* __restrict__ src,
                              const int* __restrict__ dst, int E) {
    int i = blockIdx.x * blockDim.x + threadIdx.x;
    if (i < E) {
        atomicAdd(&g_co[__ldg(&src[i])], 1);
        atomicAdd(&g_ci[__ldg(&dst[i])], 1);
    }
}
__global__ void scan1_kernel(int n) {
    __shared__ int s[SCAN_BS];
    int t = threadIdx.x, i = blockIdx.x * SCAN_BS + t;
    int v = (i < n) ? g_ci[i] : 0;
    s[t] = v; __syncthreads();
#pragma unroll
    for (int off = 1; off < SCAN_BS; off <<= 1) {
        int x = (t >= off) ? s[t - off] : 0; __syncthreads();
        s[t] += x; __syncthreads();
    }
    if (i < n) g_rowptr[i] = s[t] - v;
    if (t == SCAN_BS - 1) g_bsum[blockIdx.x] = s[t];
}
__global__ void scan2_kernel(int nb) {
    __shared__ int s[512];
    int t = threadIdx.x;
    int v = (t < nb) ? g_bsum[t] : 0;
    s[t] = v; __syncthreads();
#pragma unroll
    for (int off = 1; off < 512; off <<= 1) {
        int x = (t >= off) ? s[t - off] : 0; __syncthreads();
        s[t] += x; __syncthreads();
    }
    if (t < nb) g_bsum[t] = s[t] - v;
}
__global__ void scan3_kernel(int n, int E) {
    int i = blockIdx.x * blockDim.x + threadIdx.x;
    if (i < n) {
        int r = g_rowptr[i] + g_bsum[i >> 8];
        g_rowptr[i] = r; g_cursor[i] = r;
    }
    if (i == 0) g_rowptr[n] = E;
}
__global__ void fill_kernel(const int* __restrict__ src,
                            const int* __restrict__ dst, int E) {
    int e = blockIdx.x * blockDim.x + threadIdx.x;
    if (e < E) {
        int pos = atomicAdd(&g_cursor[__ldg(&dst[e])], 1);
        g_esrc[pos] = __ldg(&src[e]);
    }
}

// ---------------- Weight prep: transpose to [n][k], fp16 ----------------
__global__ void prep_w_kernel(const float* __restrict__ W1,
                              const float* __restrict__ W2) {
    int i = blockIdx.x * blockDim.x + threadIdx.x;
    if (i < FD * FD) {
        int k = i >> 7, n = i & 127;
        g_w1h[n * FD + k] = __float2half(W1[i]);
        g_w2h[n * FD + k] = __float2half(W2[i]);
    }
}

// ---------------- Message scale: g_hh[i,:] *= ns[i] (layer 1 only) -----------
__global__ void scale_msg_kernel(int nvec) {
    int i = blockIdx.x * blockDim.x + threadIdx.x;   // nvec = M * 16
    if (i >= nvec) return;
    int node = i >> 4;                               // 16 uint4 per row
    float ns = rsqrtf(fmaxf((float)__ldg(&g_co[node]), 1.f));
    uint4 v = reinterpret_cast<uint4*>(g_hh)[i];
    uint32_t* w = &v.x;
#pragma unroll
    for (int q = 0; q < 4; q++) {
        float2 f = __half22float2(*reinterpret_cast<__half2*>(&w[q]));
        __half2 r = __floats2half2_rn(f.x * ns, f.y * ns);
        w[q] = *reinterpret_cast<uint32_t*>(&r);
    }
    reinterpret_cast<uint4*>(g_hh)[i] = v;
}

// ---------------- fp16 mma.sync GEMM: g_hh = A16 @ W16 (fp32 acc) ------------
// Layer 1: A = fp16(features) — UNSCALED (ns applied by scale_msg afterwards).
// Layer 2: A = g_aggh (fp16, *ns folded) — straight copy.
#define ASTRIDE 136
#define TILE_B (128 * ASTRIDE * 2)   // 34816 bytes
#define OFF_A 0
#define OFF_B TILE_B
#define GEMM_SMEM (2 * TILE_B)       // 69632 bytes

__global__ __launch_bounds__(256) void gemm_mma_kernel(
    const float* __restrict__ Aext, int layer, int M) {
    extern __shared__ char sm[];
    const uint32_t sb = smem_u32(sm);
    const int tid = threadIdx.x;
    const int lane = tid & 31;
    const int wid = tid >> 5;
    const int row0 = blockIdx.x * 128;

    // ---- Fill A tile: thread handles row tid/2, 64-col half ----
    {
        int r = tid >> 1;
        int cs = (tid & 1) * 64;
        int grow = row0 + r;
        uint32_t base = (uint32_t)(r * ASTRIDE + cs) * 2;
        if (layer == 1) {
            if (grow < M) {
                const float4* ap = reinterpret_cast<const float4*>(Aext + (size_t)grow * FD + cs);
#pragma unroll
                for (int j = 0; j < 16; j++) {
                    float4 v = __ldg(&ap[j]);
                    __half2 p0 = __floats2half2_rn(v.x, v.y);
                    __half2 p1 = __floats2half2_rn(v.z, v.w);
                    uint32_t o = base + j * 8;
                    *reinterpret_cast<uint32_t*>(sm + OFF_A + o)     = *reinterpret_cast<uint32_t*>(&p0);
                    *reinterpret_cast<uint32_t*>(sm + OFF_A + o + 4) = *reinterpret_cast<uint32_t*>(&p1);
                }
            } else {
#pragma unroll
                for (int j = 0; j < 16; j++) {
                    uint32_t o = base + j * 8;
                    *reinterpret_cast<uint32_t*>(sm + OFF_A + o)     = 0u;
                    *reinterpret_cast<uint32_t*>(sm + OFF_A + o + 4) = 0u;
                }
            }
        } else {
            if (grow < M) {
                const uint4* ap = reinterpret_cast<const uint4*>(g_aggh + (size_t)grow * FD + cs);
#pragma unroll
                for (int j = 0; j < 8; j++)
                    *reinterpret_cast<uint4*>(sm + OFF_A + base + j * 16) = __ldg(&ap[j]);
            } else {
#pragma unroll
                for (int j = 0; j < 8; j++)
                    *reinterpret_cast<uint4*>(sm + OFF_A + base + j * 16) =
                        make_uint4(0u, 0u, 0u, 0u);
            }
        }
    }
    // ---- Fill B tile from pre-transposed fp16 weights [n][k] ----
    {
        const __half* wh = (layer == 1) ? g_w1h : g_w2h;
        int n = tid >> 1;
        int cs = (tid & 1) * 64;
        uint32_t base = (uint32_t)(n * ASTRIDE + cs) * 2;
        const uint4* ph = reinterpret_cast<const uint4*>(wh + (size_t)n * FD + cs);
#pragma unroll
        for (int j = 0; j < 8; j++)
            *reinterpret_cast<uint4*>(sm + OFF_B + base + j * 16) = __ldg(&ph[j]);
    }
    __syncthreads();

    // ---- Mainloop: warp tile 64x32, 8 warps (2x4) ----
    const int m0 = (wid >> 2) * 64;
    const int n0 = (wid & 3) * 32;

    float acc[4][4][4];
#pragma unroll
    for (int mi = 0; mi < 4; mi++)
#pragma unroll
        for (int ni = 0; ni < 4; ni++)
#pragma unroll
            for (int q = 0; q < 4; q++) acc[mi][ni][q] = 0.f;

    const uint32_t aOff = (uint32_t)((m0 + (lane & 15)) * ASTRIDE + ((lane >> 4) << 3)) * 2;
    const uint32_t bOff = (uint32_t)((n0 + (lane & 7)) * ASTRIDE + (((lane >> 3) & 1) << 3)) * 2;
    const uint32_t aBase = sb + OFF_A + aOff;
    const uint32_t bBase = sb + OFF_B + bOff;

#pragma unroll
    for (int ks = 0; ks < 8; ks++) {
        const uint32_t ka = ks * 32;
        uint32_t a[4][4], b[4][2];
#pragma unroll
        for (int mi = 0; mi < 4; mi++)
            LDSM4(a[mi][0], a[mi][1], a[mi][2], a[mi][3], aBase + mi * (16 * ASTRIDE * 2) + ka);
#pragma unroll
        for (int ni = 0; ni < 4; ni++)
            LDSM2(b[ni][0], b[ni][1], bBase + ni * (8 * ASTRIDE * 2) + ka);
#pragma unroll
        for (int mi = 0; mi < 4; mi++)
#pragma unroll
            for (int ni = 0; ni < 4; ni++)
                mma16816(acc[mi][ni], a[mi], b[ni]);
    }

    // ---- Epilogue: fragment -> g_hh (fp16) ----
    const int rb = m0 + (lane >> 2);
    const int cb = n0 + (lane & 3) * 2;
#pragma unroll
    for (int mi = 0; mi < 4; mi++) {
        int r0g = row0 + rb + mi * 16;
#pragma unroll
        for (int ni = 0; ni < 4; ni++) {
            int col = cb + ni * 8;
            if (r0g < M)
                *reinterpret_cast<__half2*>(g_hh + (size_t)r0g * FD + col) =
                    __floats2half2_rn(acc[mi][ni][0], acc[mi][ni][1]);
            if (r0g + 8 < M)
                *reinterpret_cast<__half2*>(g_hh + (size_t)(r0g + 8) * FD + col) =
                    __floats2half2_rn(acc[mi][ni][2], acc[mi][ni][3]);
        }
    }
}

// ---------------- CSR aggregate (R8-proven verbatim) -------------------------
// Layer 1 (out==nullptr): g_aggh = fp16(relu(acc*nd + b) * ns)
// Layer 2: out = acc*nd + b  (fp32)
__global__ __launch_bounds__(256) void agg_kernel(
    const float* __restrict__ bvec, float* __restrict__ out, int M) {
    const int warp = (blockIdx.x * blockDim.x + threadIdx.x) >> 5;
    const int lane = threadIdx.x & 31;
    if (warp >= M) return;

    const int beg = __ldg(&g_rowptr[warp]);
    const int end = __ldg(&g_rowptr[warp + 1]);

    float4 acc = make_float4(0.f, 0.f, 0.f, 0.f);
    int j = beg;
    for (; j + 3 < end; j += 4) {
        int s0 = __ldg(&g_esrc[j]);
        int s1 = __ldg(&g_esrc[j + 1]);
        int s2 = __ldg(&g_esrc[j + 2]);
        int s3 = __ldg(&g_esrc[j + 3]);
        uint2 u0 = __ldg(reinterpret_cast<const uint2*>(g_hh + (size_t)s0 * FD) + lane);
        uint2 u1 = __ldg(reinterpret_cast<const uint2*>(g_hh + (size_t)s1 * FD) + lane);
        uint2 u2 = __ldg(reinterpret_cast<const uint2*>(g_hh + (size_t)s2 * FD) + lane);
        uint2 u3 = __ldg(reinterpret_cast<const uint2*>(g_hh + (size_t)s3 * FD) + lane);
#pragma unroll
        for (int q = 0; q < 4; q++) {
            uint2 u = (q == 0) ? u0 : (q == 1) ? u1 : (q == 2) ? u2 : u3;
            float2 fa = __half22float2(*reinterpret_cast<__half2*>(&u.x));
            float2 fb = __half22float2(*reinterpret_cast<__half2*>(&u.y));
            acc.x += fa.x; acc.y += fa.y; acc.z += fb.x; acc.w += fb.y;
        }
    }
    for (; j < end; j++) {
        int s0 = __ldg(&g_esrc[j]);
        uint2 u = __ldg(reinterpret_cast<const uint2*>(g_hh + (size_t)s0 * FD) + lane);
        float2 fa = __half22float2(*reinterpret_cast<__half2*>(&u.x));
        float2 fb = __half22float2(*reinterpret_cast<__half2*>(&u.y));
        acc.x += fa.x; acc.y += fa.y; acc.z += fb.x; acc.w += fb.y;
    }

    const float nd = rsqrtf(fmaxf((float)__ldg(&g_ci[warp]), 1.f));
    const float4 bb = __ldg(reinterpret_cast<const float4*>(bvec) + lane);
    acc.x = acc.x * nd + bb.x; acc.y = acc.y * nd + bb.y;
    acc.z = acc.z * nd + bb.z; acc.w = acc.w * nd + bb.w;

    if (out) {
        reinterpret_cast<float4*>(out + (size_t)warp * FD)[lane] = acc;
    } else {
        const float ns = rsqrtf(fmaxf((float)__ldg(&g_co[warp]), 1.f));
        acc.x = fmaxf(acc.x, 0.f) * ns; acc.y = fmaxf(acc.y, 0.f) * ns;
        acc.z = fmaxf(acc.z, 0.f) * ns; acc.w = fmaxf(acc.w, 0.f) * ns;
        __half2 p0 = __floats2half2_rn(acc.x, acc.y);
        __half2 p1 = __floats2half2_rn(acc.z, acc.w);
        uint2 u;
        u.x = *reinterpret_cast<uint32_t*>(&p0);
        u.y = *reinterpret_cast<uint32_t*>(&p1);
        reinterpret_cast<uint2*>(g_aggh + (size_t)warp * FD)[lane] = u;
    }
}

// ---------------- Launch ----------------
extern "C" void kernel_launch(void* const* d_in, const int* in_sizes, int n_in,
                              void* d_out, int out_size) {
    const float* features = (const float*)d_in[0];
    const int* src = (const int*)d_in[1];
    const int* dst = (const int*)d_in[2];
    const float* W1 = (const float*)d_in[3];
    const float* b1 = (const float*)d_in[4];
    const float* W2 = (const float*)d_in[5];
    const float* b2 = (const float*)d_in[6];
    float* out = (float*)d_out;

    const int M = in_sizes[0] / FD;   // 100000
    const int E = in_sizes[1];        // 1600000

    static cudaStream_t s2 = nullptr;
    static cudaEvent_t evF = nullptr, evD = nullptr, evB = nullptr;
    if (!s2) {
        cudaStreamCreateWithFlags(&s2, cudaStreamNonBlocking);
        cudaEventCreateWithFlags(&evF, cudaEventDisableTiming);
        cudaEventCreateWithFlags(&evD, cudaEventDisableTiming);
        cudaEventCreateWithFlags(&evB, cudaEventDisableTiming);
        cudaFuncSetAttribute(gemm_mma_kernel,
                             cudaFuncAttributeMaxDynamicSharedMemorySize, GEMM_SMEM);
    }

    const int T = 256;
    const int mb = (M + T - 1) / T;
    const int eb = (E + T - 1) / T;
    const int gemm_blocks = (M + 127) / 128;        // 782
    const int agg_blocks = (M * 32 + T - 1) / T;    // one warp per node
    const int nvec = M * 16;                         // uint4 per message array
    const int svb = (nvec + T - 1) / T;

    // Fork s2 FROM the capturing (legacy) stream — required for graph capture.
    prep_w_kernel<<<(FD * FD + T - 1) / T, T>>>(W1, W2);
    cudaEventRecord(evF, (cudaStream_t)0);
    cudaStreamWaitEvent(s2, evF, 0);

    // s2: full counting/CSR chain — concurrent with gemm1 on legacy.
    zero_cnt_kernel<<<mb, T, 0, s2>>>(M);
    degree_kernel<<<eb, T, 0, s2>>>(src, dst, E);
    cudaEventRecord(evD, s2);                        // degrees ready
    scan1_kernel<<<NB1, SCAN_BS, 0, s2>>>(M);
    scan2_kernel<<<1, 512, 0, s2>>>(NB1);
    scan3_kernel<<<mb, T, 0, s2>>>(M, E);
    fill_kernel<<<eb, T, 0, s2>>>(src, dst, E);
    cudaEventRecord(evB, s2);                        // CSR ready

    // Legacy: gemm1 (no degree dependency), then scale after degrees ready.
    gemm_mma_kernel<<<gemm_blocks, 256, GEMM_SMEM>>>(features, 1, M);
    cudaStreamWaitEvent((cudaStream_t)0, evD, 0);
    scale_msg_kernel<<<svb, T>>>(nvec);

    // Join with CSR, then serial agg1 -> gemm2 -> agg2.
    cudaStreamWaitEvent((cudaStream_t)0, evB, 0);
    agg_kernel<<<agg_blocks, T>>>(b1, nullptr, M);
    gemm_mma_kernel<<<gemm_blocks, 256, GEMM_SMEM>>>(nullptr, 2, M);
    agg_kernel<<<agg_blocks, T>>>(b2, out, M);
}